// round 1
// baseline (speedup 1.0000x reference)
#include <cuda_runtime.h>
#include <cstdint>

// Problem constants (fixed by the dataset)
#define BB     2
#define CIN    32
#define COUT   32
#define KS     9
#define NIN    16384
#define NOUT   16384
#define NNZMAX 1500000

// ---------------- scratch (device globals; no allocation allowed) ----------
__device__ float g_xqT[NIN * 64];            // [i][b*32+c], qw folded in   (4 MB)
__device__ float g_z[(size_t)KS * NIN * 64]; // [k][i][b*32+o]              (37.7 MB)
__device__ int   g_count[NOUT];
__device__ int   g_offs[NOUT + 1];
__device__ int   g_cursor[NOUT];
__device__ int   g_bkey[NNZMAX];             // k*NIN + in
__device__ float g_bpsi[NNZMAX];

// ---------------- K1: transpose x*(qw) -> xqT[i][b*32+c] -------------------
// x flat: (b*32 + c)*NIN + i  (since C_IN == 32)
__global__ void k_xqT(const float* __restrict__ x, const float* __restrict__ qw) {
    __shared__ float tile[32][33];
    int i0 = blockIdx.x * 32;
    int r0 = blockIdx.y * 32;                 // r = b*32+c, 0..63
    int r = r0 + threadIdx.y;
    int i = i0 + threadIdx.x;
    tile[threadIdx.y][threadIdx.x] = x[(size_t)r * NIN + i];
    __syncthreads();
    int iw = i0 + threadIdx.y;
    g_xqT[(size_t)iw * 64 + r0 + threadIdx.x] = tile[threadIdx.x][threadIdx.y] * qw[iw];
}

// ---------------- K2: z[k][i][b*32+o] = sum_c xqT[i][b*32+c] * W[o][c][k] --
// warp per (k, 8 i's); lane = o; W column held in registers, xq broadcast via shfl
__global__ void k_z(const float* __restrict__ weight) {
    int gw   = (blockIdx.x * blockDim.x + threadIdx.x) >> 5;
    int lane = threadIdx.x & 31;
    const int CHUNKS = NIN / 8;               // 2048
    int k = gw / CHUNKS;                      // 0..8
    int ibase = (gw % CHUNKS) * 8;
    if (k >= KS) return;

    float Wreg[32];
#pragma unroll
    for (int c = 0; c < 32; c++)
        Wreg[c] = weight[lane * (CIN * KS) + c * KS + k];   // W[o=lane][c][k]

    for (int ii = 0; ii < 8; ii++) {
        int i = ibase + ii;
        float xq0 = g_xqT[(size_t)i * 64 + lane];        // b=0, c=lane
        float xq1 = g_xqT[(size_t)i * 64 + 32 + lane];   // b=1, c=lane
        float acc0 = 0.f, acc1 = 0.f;
#pragma unroll
        for (int c = 0; c < 32; c++) {
            float a = __shfl_sync(0xffffffffu, xq0, c);
            float b = __shfl_sync(0xffffffffu, xq1, c);
            acc0 = fmaf(a, Wreg[c], acc0);
            acc1 = fmaf(b, Wreg[c], acc1);
        }
        size_t zb = ((size_t)k * NIN + i) * 64;
        g_z[zb + lane]      = acc0;
        g_z[zb + 32 + lane] = acc1;
    }
}

// ---------------- K3: zero histogram ---------------------------------------
__global__ void k_zero_count() {
    int t = blockIdx.x * blockDim.x + threadIdx.x;
    if (t < NOUT) g_count[t] = 0;
}

// ---------------- K4: histogram of out indices -----------------------------
__global__ void k_hist(const int* __restrict__ idx_out, int nnz) {
    int e = blockIdx.x * blockDim.x + threadIdx.x;
    if (e < nnz) atomicAdd(&g_count[idx_out[e]], 1);
}

// ---------------- K5: exclusive scan (single block, 1024 thr, 16/thread) ---
__global__ void k_scan() {
    __shared__ int sums[1024];
    int t = threadIdx.x;
    int base = t * 16;
    int loc[16];
    int s = 0;
#pragma unroll
    for (int j = 0; j < 16; j++) { loc[j] = g_count[base + j]; s += loc[j]; }
    sums[t] = s;
    __syncthreads();
    // Hillis-Steele inclusive scan over 1024 partials
    for (int off = 1; off < 1024; off <<= 1) {
        int v = (t >= off) ? sums[t - off] : 0;
        __syncthreads();
        sums[t] += v;
        __syncthreads();
    }
    int run = (t == 0) ? 0 : sums[t - 1];
#pragma unroll
    for (int j = 0; j < 16; j++) {
        g_offs[base + j]   = run;
        g_cursor[base + j] = run;
        run += loc[j];
    }
    if (t == 1023) g_offs[NOUT] = run;
}

// ---------------- K6: scatter entries into bins ----------------------------
__global__ void k_scatter(const int* __restrict__ idx_k,
                          const int* __restrict__ idx_out,
                          const int* __restrict__ idx_in,
                          const float* __restrict__ psi, int nnz) {
    int e = blockIdx.x * blockDim.x + threadIdx.x;
    if (e < nnz) {
        int o = idx_out[e];
        int p = atomicAdd(&g_cursor[o], 1);
        g_bkey[p] = idx_k[e] * NIN + idx_in[e];
        g_bpsi[p] = psi[e];
    }
}

// ---------------- K7: gather — warp per output point -----------------------
__global__ void k_gather(const float* __restrict__ bias, float* __restrict__ out) {
    __shared__ float tile[64][33];
    int w    = threadIdx.x >> 5;
    int lane = threadIdx.x & 31;
    int n    = blockIdx.x * 32 + w;

    int s = g_offs[n];
    int e = g_offs[n + 1];
    float bv   = bias[lane];
    float acc0 = bv, acc1 = bv;

    int p = s;
    // unroll-by-2 for a bit of MLP
    for (; p + 1 < e; p += 2) {
        int   key0 = g_bkey[p];     float ps0 = g_bpsi[p];
        int   key1 = g_bkey[p + 1]; float ps1 = g_bpsi[p + 1];
        const float* z0 = &g_z[(size_t)key0 * 64];
        const float* z1 = &g_z[(size_t)key1 * 64];
        float a0 = z0[lane], a1 = z0[32 + lane];
        float b0 = z1[lane], b1 = z1[32 + lane];
        acc0 = fmaf(ps0, a0, acc0);
        acc1 = fmaf(ps0, a1, acc1);
        acc0 = fmaf(ps1, b0, acc0);
        acc1 = fmaf(ps1, b1, acc1);
    }
    if (p < e) {
        int key = g_bkey[p]; float ps = g_bpsi[p];
        const float* zp = &g_z[(size_t)key * 64];
        acc0 = fmaf(ps, zp[lane], acc0);
        acc1 = fmaf(ps, zp[32 + lane], acc1);
    }

    tile[lane][w]      = acc0;   // (b=0, o=lane)
    tile[32 + lane][w] = acc1;   // (b=1, o=lane)
    __syncthreads();

    // coalesced write: out[(b*32+o)*NOUT + n], block covers 32 consecutive n
    int n0 = blockIdx.x * 32;
    for (int v = threadIdx.x; v < 64 * 32; v += 1024) {
        int bo = v >> 5;
        int nn = v & 31;
        out[(size_t)bo * NOUT + n0 + nn] = tile[bo][nn];
    }
}

// ---------------- launch ----------------------------------------------------
extern "C" void kernel_launch(void* const* d_in, const int* in_sizes, int n_in,
                              void* d_out, int out_size) {
    const float* x    = (const float*)d_in[0];
    const float* qw   = (const float*)d_in[1];
    const float* psi  = (const float*)d_in[2];
    const float* wgt  = (const float*)d_in[3];
    const float* bias = (const float*)d_in[4];
    const int* idx_k  = (const int*)d_in[5];
    const int* idx_o  = (const int*)d_in[6];
    const int* idx_i  = (const int*)d_in[7];
    int nnz = in_sizes[2];
    float* out = (float*)d_out;

    dim3 tb(32, 32);
    k_xqT<<<dim3(NIN / 32, 64 / 32), tb>>>(x, qw);

    int zwarps  = KS * (NIN / 8);                 // 18432 warps
    int zblocks = (zwarps * 32 + 255) / 256;      // 2304 blocks
    k_z<<<zblocks, 256>>>(wgt);

    k_zero_count<<<(NOUT + 255) / 256, 256>>>();
    k_hist<<<(nnz + 255) / 256, 256>>>(idx_o, nnz);
    k_scan<<<1, 1024>>>();
    k_scatter<<<(nnz + 255) / 256, 256>>>(idx_k, idx_o, idx_i, psi, nnz);
    k_gather<<<NOUT / 32, 1024>>>(bias, out);
}

// round 3
// speedup vs baseline: 1.2064x; 1.2064x over previous
#include <cuda_runtime.h>
#include <cstdint>

// Problem constants (fixed by the dataset)
#define BB     2
#define CIN    32
#define COUT   32
#define KS     9
#define NIN    16384
#define NOUT   16384
#define NNZMAX 1500000
#define CAP    192            // padded bin capacity; Poisson(91.5) -> >10 sigma headroom

// ---------------- scratch (device globals; no allocation allowed) ----------
__device__ float g_xqT[NIN * 64];            // [i][b*32+c], qw folded in   (4 MB)
__device__ float g_z[(size_t)KS * NIN * 64]; // [k][i][b*32+o]              (37.7 MB)
__device__ int   g_cursor[NOUT];
__device__ int2  g_bin[(size_t)NOUT * CAP];  // {key = k*NIN+in, psi bits}  (25.2 MB)

// ---------------- K1: transpose x*(qw) -> xqT[i][b*32+c] -------------------
// x flat: (b*32 + c)*NIN + i  (since C_IN == 32)
__global__ void k_xqT(const float* __restrict__ x, const float* __restrict__ qw) {
    __shared__ float tile[32][33];
    int i0 = blockIdx.x * 32;
    int r0 = blockIdx.y * 32;                 // r = b*32+c, 0..63
    int r = r0 + threadIdx.y;
    int i = i0 + threadIdx.x;
    tile[threadIdx.y][threadIdx.x] = x[(size_t)r * NIN + i];
    __syncthreads();
    int iw = i0 + threadIdx.y;
    g_xqT[(size_t)iw * 64 + r0 + threadIdx.x] = tile[threadIdx.x][threadIdx.y] * qw[iw];
}

// ---------------- K2: z[k][i][b*32+o] = sum_c xqT[i][b*32+c] * W[o][c][k] --
// warp per (k, 8 i's); lane = o; W column held in registers, xq broadcast via shfl
__global__ void k_z(const float* __restrict__ weight) {
    int gw   = (blockIdx.x * blockDim.x + threadIdx.x) >> 5;
    int lane = threadIdx.x & 31;
    const int CHUNKS = NIN / 8;               // 2048
    int k = gw / CHUNKS;                      // 0..8
    int ibase = (gw % CHUNKS) * 8;
    if (k >= KS) return;

    float Wreg[32];
#pragma unroll
    for (int c = 0; c < 32; c++)
        Wreg[c] = weight[lane * (CIN * KS) + c * KS + k];   // W[o=lane][c][k]

    for (int ii = 0; ii < 8; ii++) {
        int i = ibase + ii;
        float xq0 = g_xqT[(size_t)i * 64 + lane];        // b=0, c=lane
        float xq1 = g_xqT[(size_t)i * 64 + 32 + lane];   // b=1, c=lane
        float acc0 = 0.f, acc1 = 0.f;
#pragma unroll
        for (int c = 0; c < 32; c++) {
            float a = __shfl_sync(0xffffffffu, xq0, c);
            float b = __shfl_sync(0xffffffffu, xq1, c);
            acc0 = fmaf(a, Wreg[c], acc0);
            acc1 = fmaf(b, Wreg[c], acc1);
        }
        size_t zb = ((size_t)k * NIN + i) * 64;
        g_z[zb + lane]      = acc0;
        g_z[zb + 32 + lane] = acc1;
    }
}

// ---------------- K3: zero bin cursors -------------------------------------
__global__ void k_zero_cursor() {
    int t = blockIdx.x * blockDim.x + threadIdx.x;
    if (t < NOUT) g_cursor[t] = 0;
}

// ---------------- K4: scatter entries into padded bins ---------------------
__global__ void k_scatter(const int* __restrict__ idx_k,
                          const int* __restrict__ idx_out,
                          const int* __restrict__ idx_in,
                          const float* __restrict__ psi, int nnz) {
    int e = blockIdx.x * blockDim.x + threadIdx.x;
    if (e < nnz) {
        int o = idx_out[e];
        int p = atomicAdd(&g_cursor[o], 1);
        if (p < CAP) {
            g_bin[(size_t)o * CAP + p] =
                make_int2(idx_k[e] * NIN + idx_in[e], __float_as_int(psi[e]));
        }
    }
}

// ---------------- K5: gather — warp per output point -----------------------
__global__ void k_gather(const float* __restrict__ bias, float* __restrict__ out) {
    __shared__ float tile[64][33];
    int w    = threadIdx.x >> 5;
    int lane = threadIdx.x & 31;
    int n    = blockIdx.x * 32 + w;

    int cnt = g_cursor[n];
    if (cnt > CAP) cnt = CAP;
    const int2* __restrict__ bin = &g_bin[(size_t)n * CAP];

    float bv   = bias[lane];
    float acc0 = bv, acc1 = bv;

    int p = 0;
    for (; p + 4 <= cnt; p += 4) {
        int2 e0 = bin[p];     int2 e1 = bin[p + 1];
        int2 e2 = bin[p + 2]; int2 e3 = bin[p + 3];
        const float* z0 = &g_z[(size_t)e0.x * 64];
        const float* z1 = &g_z[(size_t)e1.x * 64];
        const float* z2 = &g_z[(size_t)e2.x * 64];
        const float* z3 = &g_z[(size_t)e3.x * 64];
        float a0 = z0[lane], a1 = z0[32 + lane];
        float b0 = z1[lane], b1 = z1[32 + lane];
        float c0 = z2[lane], c1 = z2[32 + lane];
        float d0 = z3[lane], d1 = z3[32 + lane];
        float p0 = __int_as_float(e0.y), p1 = __int_as_float(e1.y);
        float p2 = __int_as_float(e2.y), p3 = __int_as_float(e3.y);
        acc0 = fmaf(p0, a0, acc0); acc1 = fmaf(p0, a1, acc1);
        acc0 = fmaf(p1, b0, acc0); acc1 = fmaf(p1, b1, acc1);
        acc0 = fmaf(p2, c0, acc0); acc1 = fmaf(p2, c1, acc1);
        acc0 = fmaf(p3, d0, acc0); acc1 = fmaf(p3, d1, acc1);
    }
    for (; p < cnt; p++) {
        int2 e = bin[p];
        const float* zp = &g_z[(size_t)e.x * 64];
        float ps = __int_as_float(e.y);
        acc0 = fmaf(ps, zp[lane], acc0);
        acc1 = fmaf(ps, zp[32 + lane], acc1);
    }

    tile[lane][w]      = acc0;   // (b=0, o=lane)
    tile[32 + lane][w] = acc1;   // (b=1, o=lane)
    __syncthreads();

    // coalesced write: out[(b*32+o)*NOUT + n], block covers 32 consecutive n
    int n0 = blockIdx.x * 32;
    for (int v = threadIdx.x; v < 64 * 32; v += 1024) {
        int bo = v >> 5;
        int nn = v & 31;
        out[(size_t)bo * NOUT + n0 + nn] = tile[bo][nn];
    }
}

// ---------------- launch ----------------------------------------------------
extern "C" void kernel_launch(void* const* d_in, const int* in_sizes, int n_in,
                              void* d_out, int out_size) {
    const float* x    = (const float*)d_in[0];
    const float* qw   = (const float*)d_in[1];
    const float* psi  = (const float*)d_in[2];
    const float* wgt  = (const float*)d_in[3];
    const float* bias = (const float*)d_in[4];
    const int* idx_k  = (const int*)d_in[5];
    const int* idx_o  = (const int*)d_in[6];
    const int* idx_i  = (const int*)d_in[7];
    int nnz = in_sizes[2];
    float* out = (float*)d_out;

    k_zero_cursor<<<(NOUT + 255) / 256, 256>>>();

    dim3 tb(32, 32);
    k_xqT<<<dim3(NIN / 32, 64 / 32), tb>>>(x, qw);

    int zwarps  = KS * (NIN / 8);                 // 18432 warps
    int zblocks = (zwarps * 32 + 255) / 256;      // 2304 blocks
    k_z<<<zblocks, 256>>>(wgt);

    k_scatter<<<(nnz + 255) / 256, 256>>>(idx_k, idx_o, idx_i, psi, nnz);
    k_gather<<<NOUT / 32, 1024>>>(bias, out);
}

// round 4
// speedup vs baseline: 1.2914x; 1.0705x over previous
#include <cuda_runtime.h>
#include <cstdint>

// Problem constants (fixed by the dataset)
#define BB     2
#define CIN    32
#define COUT   32
#define KS     9
#define NIN    16384
#define NOUT   16384
#define NNZMAX 1500000
#define CAP    192            // padded bin capacity; Poisson(91.5) -> >10 sigma headroom

// ---------------- scratch (device globals; no allocation allowed) ----------
__device__ float g_xqT[NIN * 64];            // [i][b*32+c], qw folded in   (4 MB)
__device__ float g_z[(size_t)KS * NIN * 64]; // [k][i][b*32+o]              (37.7 MB)
__device__ int   g_cursor[NOUT];
__device__ int2  g_bin[(size_t)NOUT * CAP];  // {key = k*NIN+in, psi bits}  (25.2 MB)

// ---------------- K1: transpose x*(qw) -> xqT[i][b*32+c] -------------------
__global__ void k_xqT(const float* __restrict__ x, const float* __restrict__ qw) {
    __shared__ float tile[32][33];
    int i0 = blockIdx.x * 32;
    int r0 = blockIdx.y * 32;                 // r = b*32+c, 0..63
    int r = r0 + threadIdx.y;
    int i = i0 + threadIdx.x;
    tile[threadIdx.y][threadIdx.x] = x[(size_t)r * NIN + i];
    __syncthreads();
    int iw = i0 + threadIdx.y;
    g_xqT[(size_t)iw * 64 + r0 + threadIdx.x] = tile[threadIdx.x][threadIdx.y] * qw[iw];
}

// ---------------- K2: z[k][i][b*32+o] = sum_c xqT[i][b*32+c] * W[o][c][k] --
__global__ void k_z(const float* __restrict__ weight) {
    int gw   = (blockIdx.x * blockDim.x + threadIdx.x) >> 5;
    int lane = threadIdx.x & 31;
    const int CHUNKS = NIN / 8;               // 2048
    int k = gw / CHUNKS;                      // 0..8
    int ibase = (gw % CHUNKS) * 8;
    if (k >= KS) return;

    float Wreg[32];
#pragma unroll
    for (int c = 0; c < 32; c++)
        Wreg[c] = weight[lane * (CIN * KS) + c * KS + k];   // W[o=lane][c][k]

    for (int ii = 0; ii < 8; ii++) {
        int i = ibase + ii;
        float xq0 = g_xqT[(size_t)i * 64 + lane];        // b=0, c=lane
        float xq1 = g_xqT[(size_t)i * 64 + 32 + lane];   // b=1, c=lane
        float acc0 = 0.f, acc1 = 0.f;
#pragma unroll
        for (int c = 0; c < 32; c++) {
            float a = __shfl_sync(0xffffffffu, xq0, c);
            float b = __shfl_sync(0xffffffffu, xq1, c);
            acc0 = fmaf(a, Wreg[c], acc0);
            acc1 = fmaf(b, Wreg[c], acc1);
        }
        size_t zb = ((size_t)k * NIN + i) * 64;
        g_z[zb + lane]      = acc0;
        g_z[zb + 32 + lane] = acc1;
    }
}

// ---------------- K4: scatter, 4 entries/thread for atomic ILP -------------
__global__ void k_scatter4(const int4* __restrict__ idx_k,
                           const int4* __restrict__ idx_out,
                           const int4* __restrict__ idx_in,
                           const float4* __restrict__ psi, int nq) {
    int t = blockIdx.x * blockDim.x + threadIdx.x;
    if (t < nq) {
        int4   kk = idx_k[t];
        int4   oo = idx_out[t];
        int4   ii = idx_in[t];
        float4 pp = psi[t];
        // 4 independent atomics in flight -> ~4x less exposed ATOMG latency
        int p0 = atomicAdd(&g_cursor[oo.x], 1);
        int p1 = atomicAdd(&g_cursor[oo.y], 1);
        int p2 = atomicAdd(&g_cursor[oo.z], 1);
        int p3 = atomicAdd(&g_cursor[oo.w], 1);
        if (p0 < CAP) g_bin[(size_t)oo.x * CAP + p0] = make_int2(kk.x * NIN + ii.x, __float_as_int(pp.x));
        if (p1 < CAP) g_bin[(size_t)oo.y * CAP + p1] = make_int2(kk.y * NIN + ii.y, __float_as_int(pp.y));
        if (p2 < CAP) g_bin[(size_t)oo.z * CAP + p2] = make_int2(kk.z * NIN + ii.z, __float_as_int(pp.z));
        if (p3 < CAP) g_bin[(size_t)oo.w * CAP + p3] = make_int2(kk.w * NIN + ii.w, __float_as_int(pp.w));
    }
}

// scalar tail (nnz not divisible by 4)
__global__ void k_scatter_tail(const int* __restrict__ idx_k,
                               const int* __restrict__ idx_out,
                               const int* __restrict__ idx_in,
                               const float* __restrict__ psi,
                               int start, int nnz) {
    int e = start + blockIdx.x * blockDim.x + threadIdx.x;
    if (e < nnz) {
        int o = idx_out[e];
        int p = atomicAdd(&g_cursor[o], 1);
        if (p < CAP)
            g_bin[(size_t)o * CAP + p] =
                make_int2(idx_k[e] * NIN + idx_in[e], __float_as_int(psi[e]));
    }
}

// ---------------- K5: gather — warp per output point, unroll 8 -------------
__global__ void __launch_bounds__(512) k_gather(const float* __restrict__ bias,
                                                float* __restrict__ out) {
    __shared__ float tile[64][17];
    int w    = threadIdx.x >> 5;              // 0..15
    int lane = threadIdx.x & 31;
    int n    = blockIdx.x * 16 + w;

    int cnt = g_cursor[n];
    if (cnt > CAP) cnt = CAP;
    const int2* __restrict__ bin  = &g_bin[(size_t)n * CAP];
    const int4* __restrict__ bin4 = (const int4*)bin;   // {key0,psi0,key1,psi1}

    float bv   = bias[lane];
    float acc0 = bv, acc1 = bv;

    int pairs = cnt >> 1;
    int p = 0;
    for (; p + 4 <= pairs; p += 4) {          // 8 entries, 16 z-loads in flight
        int4 q0 = bin4[p];     int4 q1 = bin4[p + 1];
        int4 q2 = bin4[p + 2]; int4 q3 = bin4[p + 3];
        const float* z0 = &g_z[(size_t)q0.x * 64];
        const float* z1 = &g_z[(size_t)q0.z * 64];
        const float* z2 = &g_z[(size_t)q1.x * 64];
        const float* z3 = &g_z[(size_t)q1.z * 64];
        const float* z4 = &g_z[(size_t)q2.x * 64];
        const float* z5 = &g_z[(size_t)q2.z * 64];
        const float* z6 = &g_z[(size_t)q3.x * 64];
        const float* z7 = &g_z[(size_t)q3.z * 64];
        float a0 = z0[lane], b0 = z0[32 + lane];
        float a1 = z1[lane], b1 = z1[32 + lane];
        float a2 = z2[lane], b2 = z2[32 + lane];
        float a3 = z3[lane], b3 = z3[32 + lane];
        float a4 = z4[lane], b4 = z4[32 + lane];
        float a5 = z5[lane], b5 = z5[32 + lane];
        float a6 = z6[lane], b6 = z6[32 + lane];
        float a7 = z7[lane], b7 = z7[32 + lane];
        acc0 = fmaf(__int_as_float(q0.y), a0, acc0); acc1 = fmaf(__int_as_float(q0.y), b0, acc1);
        acc0 = fmaf(__int_as_float(q0.w), a1, acc0); acc1 = fmaf(__int_as_float(q0.w), b1, acc1);
        acc0 = fmaf(__int_as_float(q1.y), a2, acc0); acc1 = fmaf(__int_as_float(q1.y), b2, acc1);
        acc0 = fmaf(__int_as_float(q1.w), a3, acc0); acc1 = fmaf(__int_as_float(q1.w), b3, acc1);
        acc0 = fmaf(__int_as_float(q2.y), a4, acc0); acc1 = fmaf(__int_as_float(q2.y), b4, acc1);
        acc0 = fmaf(__int_as_float(q2.w), a5, acc0); acc1 = fmaf(__int_as_float(q2.w), b5, acc1);
        acc0 = fmaf(__int_as_float(q3.y), a6, acc0); acc1 = fmaf(__int_as_float(q3.y), b6, acc1);
        acc0 = fmaf(__int_as_float(q3.w), a7, acc0); acc1 = fmaf(__int_as_float(q3.w), b7, acc1);
    }
    for (; p < pairs; p++) {
        int4 q = bin4[p];
        const float* z0 = &g_z[(size_t)q.x * 64];
        const float* z1 = &g_z[(size_t)q.z * 64];
        float a0 = z0[lane], b0 = z0[32 + lane];
        float a1 = z1[lane], b1 = z1[32 + lane];
        acc0 = fmaf(__int_as_float(q.y), a0, acc0); acc1 = fmaf(__int_as_float(q.y), b0, acc1);
        acc0 = fmaf(__int_as_float(q.w), a1, acc0); acc1 = fmaf(__int_as_float(q.w), b1, acc1);
    }
    if (cnt & 1) {
        int2 e = bin[cnt - 1];
        const float* zp = &g_z[(size_t)e.x * 64];
        float ps = __int_as_float(e.y);
        acc0 = fmaf(ps, zp[lane], acc0);
        acc1 = fmaf(ps, zp[32 + lane], acc1);
    }

    tile[lane][w]      = acc0;   // (b=0, o=lane)
    tile[32 + lane][w] = acc1;   // (b=1, o=lane)
    __syncthreads();

    int n0 = blockIdx.x * 16;
    for (int v = threadIdx.x; v < 64 * 16; v += 512) {
        int bo = v >> 4;
        int nn = v & 15;
        out[(size_t)bo * NOUT + n0 + nn] = tile[bo][nn];
    }
}

// ---------------- launch: fork scatter chain || z-build chain ---------------
extern "C" void kernel_launch(void* const* d_in, const int* in_sizes, int n_in,
                              void* d_out, int out_size) {
    const float* x    = (const float*)d_in[0];
    const float* qw   = (const float*)d_in[1];
    const float* psi  = (const float*)d_in[2];
    const float* wgt  = (const float*)d_in[3];
    const float* bias = (const float*)d_in[4];
    const int* idx_k  = (const int*)d_in[5];
    const int* idx_o  = (const int*)d_in[6];
    const int* idx_i  = (const int*)d_in[7];
    int nnz = in_sizes[2];
    float* out = (float*)d_out;

    cudaStream_t s0 = 0;
    cudaStream_t s1;
    cudaStreamCreateWithFlags(&s1, cudaStreamNonBlocking);
    cudaEvent_t evA, evB;
    cudaEventCreateWithFlags(&evA, cudaEventDisableTiming);
    cudaEventCreateWithFlags(&evB, cudaEventDisableTiming);

    int* cursor_ptr;
    cudaGetSymbolAddress((void**)&cursor_ptr, g_cursor);

    // fork: s1 does cursor reset + scatter (depends only on idx arrays)
    cudaEventRecord(evA, s0);
    cudaStreamWaitEvent(s1, evA, 0);
    cudaMemsetAsync(cursor_ptr, 0, NOUT * sizeof(int), s1);
    int nq = nnz >> 2;
    k_scatter4<<<(nq + 255) / 256, 256, 0, s1>>>(
        (const int4*)idx_k, (const int4*)idx_o, (const int4*)idx_i,
        (const float4*)psi, nq);
    int rem = nnz - (nq << 2);
    if (rem > 0)
        k_scatter_tail<<<1, 256, 0, s1>>>(idx_k, idx_o, idx_i, psi, nq << 2, nnz);
    cudaEventRecord(evB, s1);

    // main stream: z build
    dim3 tb(32, 32);
    k_xqT<<<dim3(NIN / 32, 64 / 32), tb, 0, s0>>>(x, qw);
    int zwarps  = KS * (NIN / 8);                 // 18432 warps
    int zblocks = (zwarps * 32 + 255) / 256;      // 2304 blocks
    k_z<<<zblocks, 256, 0, s0>>>(wgt);

    // join, then gather
    cudaStreamWaitEvent(s0, evB, 0);
    k_gather<<<NOUT / 16, 512, 0, s0>>>(bias, out);
}

// round 5
// speedup vs baseline: 1.4459x; 1.1196x over previous
#include <cuda_runtime.h>
#include <cuda_fp16.h>
#include <cstdint>

// Problem constants (fixed by the dataset)
#define BB     2
#define CIN    32
#define COUT   32
#define KS     9
#define NIN    16384
#define NOUT   16384
#define NNZMAX 1500000
#define CAP    192            // padded bin capacity; Poisson(91.5) -> >10 sigma

#define ZSCALE     16384.0f   // 2^14: lift z (~6e-5) into fp16 normal range
#define ZSCALE_INV 6.103515625e-05f   // 2^-14, exact

typedef unsigned long long ull;

// ---------------- f32x2 packed-math helpers (sm_103a) -----------------------
__device__ __forceinline__ ull pack2(float lo, float hi) {
    ull r; asm("mov.b64 %0,{%1,%2};" : "=l"(r) : "f"(lo), "f"(hi)); return r;
}
__device__ __forceinline__ void unpack2(ull v, float& lo, float& hi) {
    asm("mov.b64 {%0,%1},%2;" : "=f"(lo), "=f"(hi) : "l"(v));
}
__device__ __forceinline__ void fma2(ull& d, ull a, ull b) {
    asm("fma.rn.f32x2 %0,%1,%2,%0;" : "+l"(d) : "l"(a), "l"(b));
}

// ---------------- scratch (device globals; no allocation allowed) ----------
__device__ float   g_xqT[NIN * 64];             // [i][c][b] pairs, qw*2^14 folded (4 MB)
__device__ __half2 g_zh[(size_t)KS * NIN * 32]; // [key][o] = {b0,b1}          (18.9 MB)
__device__ int     g_cursor[NOUT];
__device__ int2    g_bin[(size_t)NOUT * CAP];   // {key = k*NIN+in, psi bits}  (25.2 MB)

// ---------------- K1: transpose x*(qw*2^14) -> xqT[i][c*2+b] ----------------
// x flat: (b*32 + c)*NIN + i
__global__ void k_xqT(const float* __restrict__ x, const float* __restrict__ qw) {
    __shared__ float tile[32][33];
    int i0 = blockIdx.x * 32;
    int r0 = blockIdx.y * 32;                 // r = b*32+c, 0..63
    int r = r0 + threadIdx.y;
    int i = i0 + threadIdx.x;
    tile[threadIdx.y][threadIdx.x] = x[(size_t)r * NIN + i];
    __syncthreads();
    int iw = i0 + threadIdx.y;
    int rr = r0 + threadIdx.x;
    int c = rr & 31, b = rr >> 5;
    g_xqT[(size_t)iw * 64 + c * 2 + b] = tile[threadIdx.x][threadIdx.y] * (qw[iw] * ZSCALE);
}

// ---------------- K2: z build, no shuffles ----------------------------------
// block = (chunk of 64 i's, one k). smem-staged xq tile; lane=o; packed f32x2 FMA.
__global__ void __launch_bounds__(256) k_z(const float* __restrict__ weight) {
    __shared__ alignas(16) float s_xq[64 * 64];     // 16 KB
    int k     = blockIdx.y;
    int ibase = blockIdx.x * 64;
    int tid   = threadIdx.x;
    int w     = tid >> 5;
    int lane  = tid & 31;

    // cooperative tile load (coalesced float4)
    const float4* src = (const float4*)&g_xqT[(size_t)ibase * 64];
    float4* dst = (float4*)s_xq;
    for (int v = tid; v < 64 * 64 / 4; v += 256) dst[v] = src[v];

    // W column for (o=lane, k), duplicated into f32x2 pairs
    ull Wp[32];
#pragma unroll
    for (int c = 0; c < 32; c++) {
        float wv = weight[lane * (CIN * KS) + c * KS + k];
        Wp[c] = pack2(wv, wv);
    }
    __syncthreads();

    // each warp handles 8 i's
    for (int s = 0; s < 8; s++) {
        int ii = w * 8 + s;
        const ull* row = (const ull*)&s_xq[ii * 64];  // 32 pairs {b0,b1}
        ull acc = pack2(0.f, 0.f);
#pragma unroll
        for (int c = 0; c < 32; c++)
            fma2(acc, row[c], Wp[c]);                 // {b0,b1} += xq_pair * {W,W}
        float a0, a1; unpack2(acc, a0, a1);
        size_t key = (size_t)k * NIN + (ibase + ii);
        g_zh[key * 32 + lane] = __floats2half2_rn(a0, a1);
    }
}

// ---------------- K4: scatter, 4 entries/thread for atomic ILP -------------
__global__ void k_scatter4(const int4* __restrict__ idx_k,
                           const int4* __restrict__ idx_out,
                           const int4* __restrict__ idx_in,
                           const float4* __restrict__ psi, int nq) {
    int t = blockIdx.x * blockDim.x + threadIdx.x;
    if (t < nq) {
        int4   kk = idx_k[t];
        int4   oo = idx_out[t];
        int4   ii = idx_in[t];
        float4 pp = psi[t];
        int p0 = atomicAdd(&g_cursor[oo.x], 1);
        int p1 = atomicAdd(&g_cursor[oo.y], 1);
        int p2 = atomicAdd(&g_cursor[oo.z], 1);
        int p3 = atomicAdd(&g_cursor[oo.w], 1);
        if (p0 < CAP) g_bin[(size_t)oo.x * CAP + p0] = make_int2(kk.x * NIN + ii.x, __float_as_int(pp.x));
        if (p1 < CAP) g_bin[(size_t)oo.y * CAP + p1] = make_int2(kk.y * NIN + ii.y, __float_as_int(pp.y));
        if (p2 < CAP) g_bin[(size_t)oo.z * CAP + p2] = make_int2(kk.z * NIN + ii.z, __float_as_int(pp.z));
        if (p3 < CAP) g_bin[(size_t)oo.w * CAP + p3] = make_int2(kk.w * NIN + ii.w, __float_as_int(pp.w));
    }
}

__global__ void k_scatter_tail(const int* __restrict__ idx_k,
                               const int* __restrict__ idx_out,
                               const int* __restrict__ idx_in,
                               const float* __restrict__ psi,
                               int start, int nnz) {
    int e = start + blockIdx.x * blockDim.x + threadIdx.x;
    if (e < nnz) {
        int o = idx_out[e];
        int p = atomicAdd(&g_cursor[o], 1);
        if (p < CAP)
            g_bin[(size_t)o * CAP + p] =
                make_int2(idx_k[e] * NIN + idx_in[e], __float_as_int(psi[e]));
    }
}

// ---------------- K5: gather — warp per output point, fp16 z ---------------
__global__ void __launch_bounds__(512) k_gather(const float* __restrict__ bias,
                                                float* __restrict__ out) {
    __shared__ float tile[64][17];
    int w    = threadIdx.x >> 5;              // 0..15
    int lane = threadIdx.x & 31;
    int n    = blockIdx.x * 16 + w;

    int cnt = g_cursor[n];
    if (cnt > CAP) cnt = CAP;
    const int2* __restrict__ bin  = &g_bin[(size_t)n * CAP];
    const int4* __restrict__ bin4 = (const int4*)bin;   // {key0,psi0,key1,psi1}

    float acc0 = 0.f, acc1 = 0.f;

    int pairs = cnt >> 1;
    int p = 0;
    for (; p + 4 <= pairs; p += 4) {          // 8 entries, 8 z-loads in flight
        int4 q0 = bin4[p];     int4 q1 = bin4[p + 1];
        int4 q2 = bin4[p + 2]; int4 q3 = bin4[p + 3];
        __half2 h0 = g_zh[(size_t)q0.x * 32 + lane];
        __half2 h1 = g_zh[(size_t)q0.z * 32 + lane];
        __half2 h2 = g_zh[(size_t)q1.x * 32 + lane];
        __half2 h3 = g_zh[(size_t)q1.z * 32 + lane];
        __half2 h4 = g_zh[(size_t)q2.x * 32 + lane];
        __half2 h5 = g_zh[(size_t)q2.z * 32 + lane];
        __half2 h6 = g_zh[(size_t)q3.x * 32 + lane];
        __half2 h7 = g_zh[(size_t)q3.z * 32 + lane];
        float2 f0 = __half22float2(h0), f1 = __half22float2(h1);
        float2 f2 = __half22float2(h2), f3 = __half22float2(h3);
        float2 f4 = __half22float2(h4), f5 = __half22float2(h5);
        float2 f6 = __half22float2(h6), f7 = __half22float2(h7);
        float p0 = __int_as_float(q0.y), p1 = __int_as_float(q0.w);
        float p2 = __int_as_float(q1.y), p3 = __int_as_float(q1.w);
        float p4 = __int_as_float(q2.y), p5 = __int_as_float(q2.w);
        float p6 = __int_as_float(q3.y), p7 = __int_as_float(q3.w);
        acc0 = fmaf(p0, f0.x, acc0); acc1 = fmaf(p0, f0.y, acc1);
        acc0 = fmaf(p1, f1.x, acc0); acc1 = fmaf(p1, f1.y, acc1);
        acc0 = fmaf(p2, f2.x, acc0); acc1 = fmaf(p2, f2.y, acc1);
        acc0 = fmaf(p3, f3.x, acc0); acc1 = fmaf(p3, f3.y, acc1);
        acc0 = fmaf(p4, f4.x, acc0); acc1 = fmaf(p4, f4.y, acc1);
        acc0 = fmaf(p5, f5.x, acc0); acc1 = fmaf(p5, f5.y, acc1);
        acc0 = fmaf(p6, f6.x, acc0); acc1 = fmaf(p6, f6.y, acc1);
        acc0 = fmaf(p7, f7.x, acc0); acc1 = fmaf(p7, f7.y, acc1);
    }
    for (; p < pairs; p++) {
        int4 q = bin4[p];
        float2 f0 = __half22float2(g_zh[(size_t)q.x * 32 + lane]);
        float2 f1 = __half22float2(g_zh[(size_t)q.z * 32 + lane]);
        float p0 = __int_as_float(q.y), p1 = __int_as_float(q.w);
        acc0 = fmaf(p0, f0.x, acc0); acc1 = fmaf(p0, f0.y, acc1);
        acc0 = fmaf(p1, f1.x, acc0); acc1 = fmaf(p1, f1.y, acc1);
    }
    if (cnt & 1) {
        int2 e = bin[cnt - 1];
        float2 f = __half22float2(g_zh[(size_t)e.x * 32 + lane]);
        float ps = __int_as_float(e.y);
        acc0 = fmaf(ps, f.x, acc0);
        acc1 = fmaf(ps, f.y, acc1);
    }

    float bv = bias[lane];
    acc0 = fmaf(acc0, ZSCALE_INV, bv);       // undo 2^14 (exact)
    acc1 = fmaf(acc1, ZSCALE_INV, bv);

    tile[lane][w]      = acc0;   // (b=0, o=lane)
    tile[32 + lane][w] = acc1;   // (b=1, o=lane)
    __syncthreads();

    int n0 = blockIdx.x * 16;
    for (int v = threadIdx.x; v < 64 * 16; v += 512) {
        int bo = v >> 4;
        int nn = v & 15;
        out[(size_t)bo * NOUT + n0 + nn] = tile[bo][nn];
    }
}

// ---------------- launch: fork scatter chain || z-build chain ---------------
extern "C" void kernel_launch(void* const* d_in, const int* in_sizes, int n_in,
                              void* d_out, int out_size) {
    const float* x    = (const float*)d_in[0];
    const float* qw   = (const float*)d_in[1];
    const float* psi  = (const float*)d_in[2];
    const float* wgt  = (const float*)d_in[3];
    const float* bias = (const float*)d_in[4];
    const int* idx_k  = (const int*)d_in[5];
    const int* idx_o  = (const int*)d_in[6];
    const int* idx_i  = (const int*)d_in[7];
    int nnz = in_sizes[2];
    float* out = (float*)d_out;

    cudaStream_t s0 = 0;
    cudaStream_t s1;
    cudaStreamCreateWithFlags(&s1, cudaStreamNonBlocking);
    cudaEvent_t evA, evB;
    cudaEventCreateWithFlags(&evA, cudaEventDisableTiming);
    cudaEventCreateWithFlags(&evB, cudaEventDisableTiming);

    int* cursor_ptr;
    cudaGetSymbolAddress((void**)&cursor_ptr, g_cursor);

    // fork: s1 does cursor reset + scatter (depends only on idx arrays)
    cudaEventRecord(evA, s0);
    cudaStreamWaitEvent(s1, evA, 0);
    cudaMemsetAsync(cursor_ptr, 0, NOUT * sizeof(int), s1);
    int nq = nnz >> 2;
    k_scatter4<<<(nq + 255) / 256, 256, 0, s1>>>(
        (const int4*)idx_k, (const int4*)idx_o, (const int4*)idx_i,
        (const float4*)psi, nq);
    int rem = nnz - (nq << 2);
    if (rem > 0)
        k_scatter_tail<<<1, 256, 0, s1>>>(idx_k, idx_o, idx_i, psi, nq << 2, nnz);
    cudaEventRecord(evB, s1);

    // main stream: z build
    dim3 tb(32, 32);
    k_xqT<<<dim3(NIN / 32, 64 / 32), tb, 0, s0>>>(x, qw);
    k_z<<<dim3(NIN / 64, KS), 256, 0, s0>>>(wgt);

    // join, then gather
    cudaStreamWaitEvent(s0, evB, 0);
    k_gather<<<NOUT / 16, 512, 0, s0>>>(bias, out);
}

// round 6
// speedup vs baseline: 1.8826x; 1.3020x over previous
#include <cuda_runtime.h>
#include <cuda_fp16.h>
#include <cstdint>

// Problem constants (fixed by the dataset)
#define BB     2
#define CIN    32
#define COUT   32
#define KS     9
#define NIN    16384            // == 2^14
#define NOUT   16384
#define NNZMAX 1500000
#define CAPK   40               // per-(out,k) bin capacity; Poisson(10.2) -> ~7 sigma

#define ZSCALE     16384.0f     // 2^14: lift xq (~6e-5) into fp16 normal range
#define ZSCALE_INV 6.103515625e-05f   // 2^-14, exact

// ---------------- scratch (device globals; no allocation allowed) ----------
__device__ __half g_xqh[NIN * 64];                 // [i][c][b] fp16, qw*2^14 folded (2 MB)
__device__ float  g_wT[KS * 32 * 32];              // [k][c][o]                      (36 KB)
__device__ int    g_cur9[NOUT * KS];               // per-(out,k) cursors           (0.6 MB)
__device__ int2   g_bin[(size_t)NOUT * KS * CAPK]; // {in, psi bits}                (47 MB)

// ---------------- K1: transpose x*(qw*2^14) -> xqh[i][c][b] fp16 ------------
// x flat: (b*32 + c)*NIN + i
__global__ void k_xqT(const float* __restrict__ x, const float* __restrict__ qw) {
    __shared__ float tile[32][33];
    int i0 = blockIdx.x * 32;
    int r0 = blockIdx.y * 32;                 // r = b*32+c, 0..63
    int r = r0 + threadIdx.y;
    int i = i0 + threadIdx.x;
    tile[threadIdx.y][threadIdx.x] = x[(size_t)r * NIN + i];
    __syncthreads();
    int iw = i0 + threadIdx.y;
    int rr = r0 + threadIdx.x;
    int c = rr & 31, b = rr >> 5;
    float v = tile[threadIdx.x][threadIdx.y] * (qw[iw] * ZSCALE);
    g_xqh[((size_t)iw * 32 + c) * 2 + b] = __float2half_rn(v);
}

// ---------------- K2: transpose weight -> wT[k][c][o] -----------------------
__global__ void k_wT(const float* __restrict__ weight) {
    int idx = blockIdx.x * blockDim.x + threadIdx.x;
    if (idx < KS * 32 * 32) {
        int o = idx & 31;
        int c = (idx >> 5) & 31;
        int k = idx >> 10;
        g_wT[idx] = weight[o * (CIN * KS) + c * KS + k];
    }
}

// ---------------- K3: scatter into (out,k) bins, 4 entries/thread ----------
__global__ void k_scatter4(const int4* __restrict__ idx_k,
                           const int4* __restrict__ idx_out,
                           const int4* __restrict__ idx_in,
                           const float4* __restrict__ psi, int nq) {
    int t = blockIdx.x * blockDim.x + threadIdx.x;
    if (t < nq) {
        int4   kk = idx_k[t];
        int4   oo = idx_out[t];
        int4   ii = idx_in[t];
        float4 pp = psi[t];
        int b0 = oo.x * KS + kk.x;
        int b1 = oo.y * KS + kk.y;
        int b2 = oo.z * KS + kk.z;
        int b3 = oo.w * KS + kk.w;
        int p0 = atomicAdd(&g_cur9[b0], 1);
        int p1 = atomicAdd(&g_cur9[b1], 1);
        int p2 = atomicAdd(&g_cur9[b2], 1);
        int p3 = atomicAdd(&g_cur9[b3], 1);
        if (p0 < CAPK) g_bin[(size_t)b0 * CAPK + p0] = make_int2(ii.x, __float_as_int(pp.x));
        if (p1 < CAPK) g_bin[(size_t)b1 * CAPK + p1] = make_int2(ii.y, __float_as_int(pp.y));
        if (p2 < CAPK) g_bin[(size_t)b2 * CAPK + p2] = make_int2(ii.z, __float_as_int(pp.z));
        if (p3 < CAPK) g_bin[(size_t)b3 * CAPK + p3] = make_int2(ii.w, __float_as_int(pp.w));
    }
}

__global__ void k_scatter_tail(const int* __restrict__ idx_k,
                               const int* __restrict__ idx_out,
                               const int* __restrict__ idx_in,
                               const float* __restrict__ psi,
                               int start, int nnz) {
    int e = start + blockIdx.x * blockDim.x + threadIdx.x;
    if (e < nnz) {
        int b = idx_out[e] * KS + idx_k[e];
        int p = atomicAdd(&g_cur9[b], 1);
        if (p < CAPK)
            g_bin[(size_t)b * CAPK + p] = make_int2(idx_in[e], __float_as_int(psi[e]));
    }
}

// ---------------- K4: fused gather + weight-mix -----------------------------
// Persistent-ish: grid=296, 512 thr (16 warps), warp per output point n.
// smem: Ws[9216] fp32 (36KB) | ys[16][288] float2 (36.8KB) | tile 64x17 (4.3KB)
#define GBLOCKS 296
#define NCHUNKS (NOUT / 16)      // 1024 chunks of 16 n's

__global__ void __launch_bounds__(512) k_gather(const float* __restrict__ bias,
                                                float* __restrict__ out) {
    extern __shared__ char smem[];
    float*  Ws   = (float*)smem;                       // 9216 floats
    float2* ysAll = (float2*)(smem + 36864);           // 16 warps x 288
    float*  tile = (float*)(smem + 36864 + 36864);     // 64 x 17

    int tid  = threadIdx.x;
    int w    = tid >> 5;
    int lane = tid & 31;

    // stage W once per block (coalesced float4)
    {
        const float4* src = (const float4*)g_wT;
        float4* dst = (float4*)Ws;
        for (int v = tid; v < (KS * 32 * 32) / 4; v += 512) dst[v] = src[v];
    }
    __syncthreads();

    float bv = bias[lane];
    float2* ysW = &ysAll[(size_t)w * 288];
    const __half2* __restrict__ xq2 = (const __half2*)g_xqh;

    for (int chunk = blockIdx.x; chunk < NCHUNKS; chunk += GBLOCKS) {
        int n = chunk * 16 + w;

        // ---- accumulate per-k partial sums over this n's (k) segments ----
#pragma unroll
        for (int k = 0; k < KS; k++) {
            int base = n * KS + k;
            int cnt = g_cur9[base];
            if (cnt > CAPK) cnt = CAPK;
            const int4* seg = (const int4*)&g_bin[(size_t)base * CAPK];
            float a0 = 0.f, a1 = 0.f;

            int pairs = cnt >> 1;
            int p = 0;
            for (; p + 2 <= pairs; p += 2) {            // 4 entries in flight
                int4 q0 = seg[p];
                int4 q1 = seg[p + 1];
                float2 f0 = __half22float2(xq2[(size_t)q0.x * 32 + lane]);
                float2 f1 = __half22float2(xq2[(size_t)q0.z * 32 + lane]);
                float2 f2 = __half22float2(xq2[(size_t)q1.x * 32 + lane]);
                float2 f3 = __half22float2(xq2[(size_t)q1.z * 32 + lane]);
                float p0 = __int_as_float(q0.y), p1 = __int_as_float(q0.w);
                float p2 = __int_as_float(q1.y), p3 = __int_as_float(q1.w);
                a0 = fmaf(p0, f0.x, a0); a1 = fmaf(p0, f0.y, a1);
                a0 = fmaf(p1, f1.x, a0); a1 = fmaf(p1, f1.y, a1);
                a0 = fmaf(p2, f2.x, a0); a1 = fmaf(p2, f2.y, a1);
                a0 = fmaf(p3, f3.x, a0); a1 = fmaf(p3, f3.y, a1);
            }
            for (; p < pairs; p++) {
                int4 q = seg[p];
                float2 f0 = __half22float2(xq2[(size_t)q.x * 32 + lane]);
                float2 f1 = __half22float2(xq2[(size_t)q.z * 32 + lane]);
                float p0 = __int_as_float(q.y), p1 = __int_as_float(q.w);
                a0 = fmaf(p0, f0.x, a0); a1 = fmaf(p0, f0.y, a1);
                a0 = fmaf(p1, f1.x, a0); a1 = fmaf(p1, f1.y, a1);
            }
            if (cnt & 1) {
                int2 e = ((const int2*)seg)[cnt - 1];
                float2 f = __half22float2(xq2[(size_t)e.x * 32 + lane]);
                float ps = __int_as_float(e.y);
                a0 = fmaf(ps, f.x, a0); a1 = fmaf(ps, f.y, a1);
            }
            ysW[k * 32 + lane] = make_float2(a0, a1);   // lane holds c
        }
        __syncwarp();

        // ---- mix: out[o=lane] = sum_{k,c} W[k][c][o] * y[k][c] ----
        float acc0 = 0.f, acc1 = 0.f;
#pragma unroll 4
        for (int j = 0; j < 288; j++) {
            float2 y2 = ysW[j];                 // broadcast LDS.64
            float wv  = Ws[j * 32 + lane];      // conflict-free LDS.32
            acc0 = fmaf(y2.x, wv, acc0);
            acc1 = fmaf(y2.y, wv, acc1);
        }
        acc0 = fmaf(acc0, ZSCALE_INV, bv);
        acc1 = fmaf(acc1, ZSCALE_INV, bv);

        tile[lane * 17 + w]        = acc0;      // (b=0, o=lane)
        tile[(32 + lane) * 17 + w] = acc1;      // (b=1, o=lane)
        __syncthreads();

        int n0 = chunk * 16;
        for (int v = tid; v < 64 * 16; v += 512) {
            int bo = v >> 4;
            int nn = v & 15;
            out[(size_t)bo * NOUT + n0 + nn] = tile[bo * 17 + nn];
        }
        __syncthreads();                        // tile reuse guard
    }
}

#define GATHER_SMEM (36864 + 36864 + 64 * 17 * 4)

// ---------------- launch: fork scatter chain || prep chain ------------------
extern "C" void kernel_launch(void* const* d_in, const int* in_sizes, int n_in,
                              void* d_out, int out_size) {
    const float* x    = (const float*)d_in[0];
    const float* qw   = (const float*)d_in[1];
    const float* psi  = (const float*)d_in[2];
    const float* wgt  = (const float*)d_in[3];
    const float* bias = (const float*)d_in[4];
    const int* idx_k  = (const int*)d_in[5];
    const int* idx_o  = (const int*)d_in[6];
    const int* idx_i  = (const int*)d_in[7];
    int nnz = in_sizes[2];
    float* out = (float*)d_out;

    cudaFuncSetAttribute(k_gather, cudaFuncAttributeMaxDynamicSharedMemorySize,
                         GATHER_SMEM);

    cudaStream_t s0 = 0;
    cudaStream_t s1;
    cudaStreamCreateWithFlags(&s1, cudaStreamNonBlocking);
    cudaEvent_t evA, evB;
    cudaEventCreateWithFlags(&evA, cudaEventDisableTiming);
    cudaEventCreateWithFlags(&evB, cudaEventDisableTiming);

    int* cur_ptr;
    cudaGetSymbolAddress((void**)&cur_ptr, g_cur9);

    // fork: s1 = cursor reset + scatter (depends only on idx arrays)
    cudaEventRecord(evA, s0);
    cudaStreamWaitEvent(s1, evA, 0);
    cudaMemsetAsync(cur_ptr, 0, NOUT * KS * sizeof(int), s1);
    int nq = nnz >> 2;
    k_scatter4<<<(nq + 255) / 256, 256, 0, s1>>>(
        (const int4*)idx_k, (const int4*)idx_o, (const int4*)idx_i,
        (const float4*)psi, nq);
    int rem = nnz - (nq << 2);
    if (rem > 0)
        k_scatter_tail<<<1, 256, 0, s1>>>(idx_k, idx_o, idx_i, psi, nq << 2, nnz);
    cudaEventRecord(evB, s1);

    // main stream: xq + wT prep (k_z no longer exists)
    dim3 tb(32, 32);
    k_xqT<<<dim3(NIN / 32, 64 / 32), tb, 0, s0>>>(x, qw);
    k_wT<<<(KS * 32 * 32 + 255) / 256, 256, 0, s0>>>(wgt);

    // join, then fused gather+mix
    cudaStreamWaitEvent(s0, evB, 0);
    k_gather<<<GBLOCKS, 512, GATHER_SMEM, s0>>>(bias, out);
}

// round 7
// speedup vs baseline: 1.9919x; 1.0581x over previous
#include <cuda_runtime.h>
#include <cuda_fp16.h>
#include <cstdint>

// Problem constants (fixed by the dataset)
#define BB     2
#define CIN    32
#define COUT   32
#define KS     9
#define NIN    16384
#define NOUT   16384
#define NNZMAX 1500000
#define CAPK   40               // per-(out,k) bin capacity; Poisson(10.2) -> ~7 sigma
#define KPAD   16               // cursor/bin k-stride padding (int4-friendly)

#define ZSCALE     16384.0f     // 2^14: lift xq (~6e-5) into fp16 normal range
#define ZSCALE_INV 6.103515625e-05f   // 2^-14, exact

// ---------------- scratch (device globals; no allocation allowed) ----------
__device__ __half g_xqh[NIN * 64];                   // [i][c][b] fp16, qw*2^14 folded (2 MB)
__device__ float  g_wT[KS * 32 * 32];                // [k][c][o]                     (36 KB)
__device__ int    g_cur[NOUT * KPAD];                // per-(out,k) cursors, pad 16   (1 MB)
__device__ int2   g_bin[(size_t)NOUT * KPAD * CAPK]; // {in, psi bits}                (84 MB)

// ---------------- K1: transpose x*(qw*2^14) -> xqh[i][c][b] fp16 ------------
__global__ void k_xqT(const float* __restrict__ x, const float* __restrict__ qw) {
    __shared__ float tile[32][33];
    int i0 = blockIdx.x * 32;
    int r0 = blockIdx.y * 32;                 // r = b*32+c, 0..63
    int r = r0 + threadIdx.y;
    int i = i0 + threadIdx.x;
    tile[threadIdx.y][threadIdx.x] = x[(size_t)r * NIN + i];
    __syncthreads();
    int iw = i0 + threadIdx.y;
    int rr = r0 + threadIdx.x;
    int c = rr & 31, b = rr >> 5;
    float v = tile[threadIdx.x][threadIdx.y] * (qw[iw] * ZSCALE);
    g_xqh[((size_t)iw * 32 + c) * 2 + b] = __float2half_rn(v);
}

// ---------------- K2: transpose weight -> wT[k][c][o] -----------------------
__global__ void k_wT(const float* __restrict__ weight) {
    int idx = blockIdx.x * blockDim.x + threadIdx.x;
    if (idx < KS * 32 * 32) {
        int o = idx & 31;
        int c = (idx >> 5) & 31;
        int k = idx >> 10;
        g_wT[idx] = weight[o * (CIN * KS) + c * KS + k];
    }
}

// ---------------- K3: scatter into (out,k) bins, 4 entries/thread ----------
__global__ void k_scatter4(const int4* __restrict__ idx_k,
                           const int4* __restrict__ idx_out,
                           const int4* __restrict__ idx_in,
                           const float4* __restrict__ psi, int nq) {
    int t = blockIdx.x * blockDim.x + threadIdx.x;
    if (t < nq) {
        int4   kk = idx_k[t];
        int4   oo = idx_out[t];
        int4   ii = idx_in[t];
        float4 pp = psi[t];
        int b0 = (oo.x << 4) + kk.x;
        int b1 = (oo.y << 4) + kk.y;
        int b2 = (oo.z << 4) + kk.z;
        int b3 = (oo.w << 4) + kk.w;
        int p0 = atomicAdd(&g_cur[b0], 1);
        int p1 = atomicAdd(&g_cur[b1], 1);
        int p2 = atomicAdd(&g_cur[b2], 1);
        int p3 = atomicAdd(&g_cur[b3], 1);
        if (p0 < CAPK) g_bin[(size_t)b0 * CAPK + p0] = make_int2(ii.x, __float_as_int(pp.x));
        if (p1 < CAPK) g_bin[(size_t)b1 * CAPK + p1] = make_int2(ii.y, __float_as_int(pp.y));
        if (p2 < CAPK) g_bin[(size_t)b2 * CAPK + p2] = make_int2(ii.z, __float_as_int(pp.z));
        if (p3 < CAPK) g_bin[(size_t)b3 * CAPK + p3] = make_int2(ii.w, __float_as_int(pp.w));
    }
}

__global__ void k_scatter_tail(const int* __restrict__ idx_k,
                               const int* __restrict__ idx_out,
                               const int* __restrict__ idx_in,
                               const float* __restrict__ psi,
                               int start, int nnz) {
    int e = start + blockIdx.x * blockDim.x + threadIdx.x;
    if (e < nnz) {
        int b = (idx_out[e] << 4) + idx_k[e];
        int p = atomicAdd(&g_cur[b], 1);
        if (p < CAPK)
            g_bin[(size_t)b * CAPK + p] = make_int2(idx_in[e], __float_as_int(psi[e]));
    }
}

// ---------------- K4: fused gather + weight-mix -----------------------------
// 512 thr (16 warps), warp per output point n; 3 blocks/SM.
// smem: Ws[9216] fp32 (36KB) | ysAll 16x288 float2 (36.9KB, REUSED as out tile)
#define GBLOCKS 444
#define NCHUNKS (NOUT / 16)      // 1024 chunks of 16 n's

__global__ void __launch_bounds__(512, 3) k_gather(const float* __restrict__ bias,
                                                   float* __restrict__ out) {
    extern __shared__ char smem[];
    float*  Ws    = (float*)smem;                      // 9216 floats
    float2* ysAll = (float2*)(smem + 36864);           // 16 warps x 288
    float*  tile  = (float*)(smem + 36864);            // aliased: 64 x 17 floats

    int tid  = threadIdx.x;
    int w    = tid >> 5;
    int lane = tid & 31;

    // stage W once per block (coalesced float4)
    {
        const float4* src = (const float4*)g_wT;
        float4* dst = (float4*)Ws;
        for (int v = tid; v < (KS * 32 * 32) / 4; v += 512) dst[v] = src[v];
    }
    __syncthreads();

    float bv = bias[lane];
    float2* ysW = &ysAll[w * 288];
    const __half2* __restrict__ xq2 = (const __half2*)g_xqh;

    for (int chunk = blockIdx.x; chunk < NCHUNKS; chunk += GBLOCKS) {
        int n = chunk * 16 + w;

        // prefetch all 9 segment counts (one latency, not nine)
        int4 c03 = *(const int4*)&g_cur[n << 4];
        int4 c47 = *(const int4*)&g_cur[(n << 4) + 4];
        int  c8  = g_cur[(n << 4) + 8];
        int cnts[KS] = {c03.x, c03.y, c03.z, c03.w, c47.x, c47.y, c47.z, c47.w, c8};

        // ---- accumulate per-k partial sums over this n's segments ----
#pragma unroll
        for (int k = 0; k < KS; k++) {
            int cnt = cnts[k];
            if (cnt > CAPK) cnt = CAPK;
            const int4* seg = (const int4*)&g_bin[(size_t)((n << 4) + k) * CAPK];
            float a0 = 0.f, a1 = 0.f;

            int pairs = cnt >> 1;
            int p = 0;
            for (; p + 2 <= pairs; p += 2) {            // 4 entries in flight
                int4 q0 = seg[p];
                int4 q1 = seg[p + 1];
                float2 f0 = __half22float2(xq2[(q0.x << 5) + lane]);
                float2 f1 = __half22float2(xq2[(q0.z << 5) + lane]);
                float2 f2 = __half22float2(xq2[(q1.x << 5) + lane]);
                float2 f3 = __half22float2(xq2[(q1.z << 5) + lane]);
                float p0 = __int_as_float(q0.y), p1 = __int_as_float(q0.w);
                float p2 = __int_as_float(q1.y), p3 = __int_as_float(q1.w);
                a0 = fmaf(p0, f0.x, a0); a1 = fmaf(p0, f0.y, a1);
                a0 = fmaf(p1, f1.x, a0); a1 = fmaf(p1, f1.y, a1);
                a0 = fmaf(p2, f2.x, a0); a1 = fmaf(p2, f2.y, a1);
                a0 = fmaf(p3, f3.x, a0); a1 = fmaf(p3, f3.y, a1);
            }
            for (; p < pairs; p++) {
                int4 q = seg[p];
                float2 f0 = __half22float2(xq2[(q.x << 5) + lane]);
                float2 f1 = __half22float2(xq2[(q.z << 5) + lane]);
                float p0 = __int_as_float(q.y), p1 = __int_as_float(q.w);
                a0 = fmaf(p0, f0.x, a0); a1 = fmaf(p0, f0.y, a1);
                a0 = fmaf(p1, f1.x, a0); a1 = fmaf(p1, f1.y, a1);
            }
            if (cnt & 1) {
                int2 e = ((const int2*)seg)[cnt - 1];
                float2 f = __half22float2(xq2[(e.x << 5) + lane]);
                float ps = __int_as_float(e.y);
                a0 = fmaf(ps, f.x, a0); a1 = fmaf(ps, f.y, a1);
            }
            ysW[k * 32 + lane] = make_float2(a0, a1);   // lane holds c
        }
        __syncwarp();

        // ---- mix: out[o=lane] = sum_{k,c} W[k][c][o] * y[k][c] ----
        float acc0 = 0.f, acc1 = 0.f;
#pragma unroll 8
        for (int j = 0; j < 288; j++) {
            float2 y2 = ysW[j];                 // broadcast LDS.64
            float wv  = Ws[j * 32 + lane];      // conflict-free LDS.32
            acc0 = fmaf(y2.x, wv, acc0);
            acc1 = fmaf(y2.y, wv, acc1);
        }
        acc0 = fmaf(acc0, ZSCALE_INV, bv);
        acc1 = fmaf(acc1, ZSCALE_INV, bv);

        __syncthreads();                        // everyone done reading ys
        tile[lane * 17 + w]        = acc0;      // (b=0, o=lane)  [aliases ys]
        tile[(32 + lane) * 17 + w] = acc1;      // (b=1, o=lane)
        __syncthreads();

        int n0 = chunk * 16;
        for (int v = tid; v < 64 * 16; v += 512) {
            int bo = v >> 4;
            int nn = v & 15;
            out[(size_t)bo * NOUT + n0 + nn] = tile[bo * 17 + nn];
        }
        __syncthreads();                        // tile dead before next ys write
    }
}

#define GATHER_SMEM (36864 + 36864)

// ---------------- launch: fork scatter chain || prep chain ------------------
extern "C" void kernel_launch(void* const* d_in, const int* in_sizes, int n_in,
                              void* d_out, int out_size) {
    const float* x    = (const float*)d_in[0];
    const float* qw   = (const float*)d_in[1];
    const float* psi  = (const float*)d_in[2];
    const float* wgt  = (const float*)d_in[3];
    const float* bias = (const float*)d_in[4];
    const int* idx_k  = (const int*)d_in[5];
    const int* idx_o  = (const int*)d_in[6];
    const int* idx_i  = (const int*)d_in[7];
    int nnz = in_sizes[2];
    float* out = (float*)d_out;

    cudaFuncSetAttribute(k_gather, cudaFuncAttributeMaxDynamicSharedMemorySize,
                         GATHER_SMEM);

    cudaStream_t s0 = 0;
    cudaStream_t s1;
    cudaStreamCreateWithFlags(&s1, cudaStreamNonBlocking);
    cudaEvent_t evA, evB;
    cudaEventCreateWithFlags(&evA, cudaEventDisableTiming);
    cudaEventCreateWithFlags(&evB, cudaEventDisableTiming);

    int* cur_ptr;
    cudaGetSymbolAddress((void**)&cur_ptr, g_cur);

    // fork: s1 = cursor reset + scatter (depends only on idx arrays)
    cudaEventRecord(evA, s0);
    cudaStreamWaitEvent(s1, evA, 0);
    cudaMemsetAsync(cur_ptr, 0, NOUT * KPAD * sizeof(int), s1);
    int nq = nnz >> 2;
    k_scatter4<<<(nq + 255) / 256, 256, 0, s1>>>(
        (const int4*)idx_k, (const int4*)idx_o, (const int4*)idx_i,
        (const float4*)psi, nq);
    int rem = nnz - (nq << 2);
    if (rem > 0)
        k_scatter_tail<<<1, 256, 0, s1>>>(idx_k, idx_o, idx_i, psi, nq << 2, nnz);
    cudaEventRecord(evB, s1);

    // main stream: xq + wT prep
    dim3 tb(32, 32);
    k_xqT<<<dim3(NIN / 32, 64 / 32), tb, 0, s0>>>(x, qw);
    k_wT<<<(KS * 32 * 32 + 255) / 256, 256, 0, s0>>>(wgt);

    // join, then fused gather+mix
    cudaStreamWaitEvent(s0, evB, 0);
    k_gather<<<GBLOCKS, 512, GATHER_SMEM, s0>>>(bias, out);
}

// round 8
// speedup vs baseline: 2.1026x; 1.0556x over previous
#include <cuda_runtime.h>
#include <cuda_fp16.h>
#include <cstdint>

// Problem constants (fixed by the dataset)
#define BB     2
#define CIN    32
#define COUT   32
#define KS     9
#define NIN    16384
#define NOUT   16384
#define NNZMAX 1500000
#define CAPK   40               // per-(out,k) bin capacity; Poisson(10.2) -> ~7 sigma
#define KPAD   16               // cursor/bin k-stride padding (int4-friendly)

#define ZSCALE     16384.0f     // 2^14: lift xq (~6e-5) into fp16 normal range
#define ZSCALE_INV 6.103515625e-05f   // 2^-14, exact

// ---------------- scratch (device globals; no allocation allowed) ----------
__device__ __half g_xqh[NIN * 64];                   // [i][c][b] fp16, qw*2^14 folded (2 MB)
__device__ float  g_wT2[KS * 32 * 32];               // pair-interleaved: [jj][o][t]  (36 KB)
__device__ int    g_cur[NOUT * KPAD];                // per-(out,k) cursors, pad 16   (1 MB)
__device__ int2   g_bin[(size_t)NOUT * KPAD * CAPK]; // {in, psi bits}                (84 MB)

// ---------------- K1: transpose x*(qw*2^14) -> xqh[i][c][b] fp16 ------------
__global__ void k_xqT(const float* __restrict__ x, const float* __restrict__ qw) {
    __shared__ float tile[32][33];
    int i0 = blockIdx.x * 32;
    int r0 = blockIdx.y * 32;                 // r = b*32+c, 0..63
    int r = r0 + threadIdx.y;
    int i = i0 + threadIdx.x;
    tile[threadIdx.y][threadIdx.x] = x[(size_t)r * NIN + i];
    __syncthreads();
    int iw = i0 + threadIdx.y;
    int rr = r0 + threadIdx.x;
    int c = rr & 31, b = rr >> 5;
    float v = tile[threadIdx.x][threadIdx.y] * (qw[iw] * ZSCALE);
    g_xqh[((size_t)iw * 32 + c) * 2 + b] = __float2half_rn(v);
}

// ---------------- K2: weight -> pair-interleaved wT2[jj][o][t] --------------
// j = k*32+c (0..287); pair jj = j>>1, t = j&1. Ws2[jj*64 + o*2 + t] = W[o][c][k]
__global__ void k_wT2(const float* __restrict__ weight) {
    int idx = blockIdx.x * blockDim.x + threadIdx.x;
    if (idx < KS * 32 * 32) {
        int t  = idx & 1;
        int o  = (idx >> 1) & 31;
        int jj = idx >> 6;
        int j  = 2 * jj + t;
        int k  = j >> 5;
        int c  = j & 31;
        g_wT2[idx] = weight[o * (CIN * KS) + c * KS + k];
    }
}

// ---------------- K3: scatter into (out,k) bins, 4 entries/thread ----------
__global__ void k_scatter4(const int4* __restrict__ idx_k,
                           const int4* __restrict__ idx_out,
                           const int4* __restrict__ idx_in,
                           const float4* __restrict__ psi, int nq) {
    int t = blockIdx.x * blockDim.x + threadIdx.x;
    if (t < nq) {
        int4   kk = idx_k[t];
        int4   oo = idx_out[t];
        int4   ii = idx_in[t];
        float4 pp = psi[t];
        int b0 = (oo.x << 4) + kk.x;
        int b1 = (oo.y << 4) + kk.y;
        int b2 = (oo.z << 4) + kk.z;
        int b3 = (oo.w << 4) + kk.w;
        int p0 = atomicAdd(&g_cur[b0], 1);
        int p1 = atomicAdd(&g_cur[b1], 1);
        int p2 = atomicAdd(&g_cur[b2], 1);
        int p3 = atomicAdd(&g_cur[b3], 1);
        if (p0 < CAPK) g_bin[(size_t)b0 * CAPK + p0] = make_int2(ii.x, __float_as_int(pp.x));
        if (p1 < CAPK) g_bin[(size_t)b1 * CAPK + p1] = make_int2(ii.y, __float_as_int(pp.y));
        if (p2 < CAPK) g_bin[(size_t)b2 * CAPK + p2] = make_int2(ii.z, __float_as_int(pp.z));
        if (p3 < CAPK) g_bin[(size_t)b3 * CAPK + p3] = make_int2(ii.w, __float_as_int(pp.w));
    }
}

__global__ void k_scatter_tail(const int* __restrict__ idx_k,
                               const int* __restrict__ idx_out,
                               const int* __restrict__ idx_in,
                               const float* __restrict__ psi,
                               int start, int nnz) {
    int e = start + blockIdx.x * blockDim.x + threadIdx.x;
    if (e < nnz) {
        int b = (idx_out[e] << 4) + idx_k[e];
        int p = atomicAdd(&g_cur[b], 1);
        if (p < CAPK)
            g_bin[(size_t)b * CAPK + p] = make_int2(idx_in[e], __float_as_int(psi[e]));
    }
}

// ---------------- K4: fused gather + weight-mix -----------------------------
// 512 thr (16 warps), warp per output point n; 3 blocks/SM.
// smem: Ws2[9216] fp32 (36KB) | ysAll 16x288 float2 (36.9KB, REUSED as out tile)
#define GBLOCKS 444
#define NCHUNKS (NOUT / 16)      // 1024 chunks of 16 n's

__global__ void __launch_bounds__(512, 3) k_gather(const float* __restrict__ bias,
                                                   float* __restrict__ out) {
    extern __shared__ char smem[];
    float*  Ws    = (float*)smem;                      // 9216 floats, pair layout
    float2* ysAll = (float2*)(smem + 36864);           // 16 warps x 288
    float*  tile  = (float*)(smem + 36864);            // aliased: 64 x 17 floats

    int tid  = threadIdx.x;
    int w    = tid >> 5;
    int lane = tid & 31;

    // stage W once per block (coalesced float4)
    {
        const float4* src = (const float4*)g_wT2;
        float4* dst = (float4*)Ws;
        for (int v = tid; v < (KS * 32 * 32) / 4; v += 512) dst[v] = src[v];
    }
    __syncthreads();

    float bv = bias[lane];
    float2* ysW = &ysAll[w * 288];
    const __half2* __restrict__ xq2 = (const __half2*)g_xqh;

    for (int chunk = blockIdx.x; chunk < NCHUNKS; chunk += GBLOCKS) {
        int n = chunk * 16 + w;

        // prefetch all 9 segment counts (one latency, not nine)
        int4 c03 = *(const int4*)&g_cur[n << 4];
        int4 c47 = *(const int4*)&g_cur[(n << 4) + 4];
        int  c8  = g_cur[(n << 4) + 8];
        int cnts[KS] = {c03.x, c03.y, c03.z, c03.w, c47.x, c47.y, c47.z, c47.w, c8};

        // ---- accumulate per-k partial sums over this n's segments ----
#pragma unroll
        for (int k = 0; k < KS; k++) {
            int cnt = cnts[k];
            if (cnt > CAPK) cnt = CAPK;
            const int4* seg = (const int4*)&g_bin[(size_t)((n << 4) + k) * CAPK];
            float a0 = 0.f, a1 = 0.f;

            int pairs = cnt >> 1;
            int p = 0;
            for (; p + 2 <= pairs; p += 2) {            // 4 entries in flight
                int4 q0 = seg[p];
                int4 q1 = seg[p + 1];
                float2 f0 = __half22float2(xq2[(q0.x << 5) + lane]);
                float2 f1 = __half22float2(xq2[(q0.z << 5) + lane]);
                float2 f2 = __half22float2(xq2[(q1.x << 5) + lane]);
                float2 f3 = __half22float2(xq2[(q1.z << 5) + lane]);
                float p0 = __int_as_float(q0.y), p1 = __int_as_float(q0.w);
                float p2 = __int_as_float(q1.y), p3 = __int_as_float(q1.w);
                a0 = fmaf(p0, f0.x, a0); a1 = fmaf(p0, f0.y, a1);
                a0 = fmaf(p1, f1.x, a0); a1 = fmaf(p1, f1.y, a1);
                a0 = fmaf(p2, f2.x, a0); a1 = fmaf(p2, f2.y, a1);
                a0 = fmaf(p3, f3.x, a0); a1 = fmaf(p3, f3.y, a1);
            }
            for (; p < pairs; p++) {
                int4 q = seg[p];
                float2 f0 = __half22float2(xq2[(q.x << 5) + lane]);
                float2 f1 = __half22float2(xq2[(q.z << 5) + lane]);
                float p0 = __int_as_float(q.y), p1 = __int_as_float(q.w);
                a0 = fmaf(p0, f0.x, a0); a1 = fmaf(p0, f0.y, a1);
                a0 = fmaf(p1, f1.x, a0); a1 = fmaf(p1, f1.y, a1);
            }
            if (cnt & 1) {
                int2 e = ((const int2*)seg)[cnt - 1];
                float2 f = __half22float2(xq2[(e.x << 5) + lane]);
                float ps = __int_as_float(e.y);
                a0 = fmaf(ps, f.x, a0); a1 = fmaf(ps, f.y, a1);
            }
            ysW[k * 32 + lane] = make_float2(a0, a1);   // lane holds c
        }
        __syncwarp();

        // ---- mix: out[o=lane] = sum_j W[j][o] * y[j], two j's per iter ----
        // ys4[jj] = {y[2jj].b0, y[2jj].b1, y[2jj+1].b0, y[2jj+1].b1} (LDS.128 bcast)
        // Wpair   = {W[2jj][o], W[2jj+1][o]}                          (LDS.64, cf)
        float acc0 = 0.f, acc1 = 0.f;
        const float4* ys4 = (const float4*)ysW;
#pragma unroll 4
        for (int jj = 0; jj < 144; jj++) {
            float4 yv = ys4[jj];
            float2 wv = *(const float2*)&Ws[jj * 64 + lane * 2];
            acc0 = fmaf(yv.x, wv.x, acc0); acc1 = fmaf(yv.y, wv.x, acc1);
            acc0 = fmaf(yv.z, wv.y, acc0); acc1 = fmaf(yv.w, wv.y, acc1);
        }
        acc0 = fmaf(acc0, ZSCALE_INV, bv);
        acc1 = fmaf(acc1, ZSCALE_INV, bv);

        __syncthreads();                        // everyone done reading ys
        tile[lane * 17 + w]        = acc0;      // (b=0, o=lane)  [aliases ys]
        tile[(32 + lane) * 17 + w] = acc1;      // (b=1, o=lane)
        __syncthreads();

        int n0 = chunk * 16;
        for (int v = tid; v < 64 * 16; v += 512) {
            int bo = v >> 4;
            int nn = v & 15;
            out[(size_t)bo * NOUT + n0 + nn] = tile[bo * 17 + nn];
        }
        __syncthreads();                        // tile dead before next ys write
    }
}

#define GATHER_SMEM (36864 + 36864)

// ---------------- launch: fork scatter chain || prep chain ------------------
extern "C" void kernel_launch(void* const* d_in, const int* in_sizes, int n_in,
                              void* d_out, int out_size) {
    const float* x    = (const float*)d_in[0];
    const float* qw   = (const float*)d_in[1];
    const float* psi  = (const float*)d_in[2];
    const float* wgt  = (const float*)d_in[3];
    const float* bias = (const float*)d_in[4];
    const int* idx_k  = (const int*)d_in[5];
    const int* idx_o  = (const int*)d_in[6];
    const int* idx_i  = (const int*)d_in[7];
    int nnz = in_sizes[2];
    float* out = (float*)d_out;

    cudaFuncSetAttribute(k_gather, cudaFuncAttributeMaxDynamicSharedMemorySize,
                         GATHER_SMEM);

    cudaStream_t s0 = 0;
    cudaStream_t s1;
    cudaStreamCreateWithFlags(&s1, cudaStreamNonBlocking);
    cudaEvent_t evA, evB;
    cudaEventCreateWithFlags(&evA, cudaEventDisableTiming);
    cudaEventCreateWithFlags(&evB, cudaEventDisableTiming);

    int* cur_ptr;
    cudaGetSymbolAddress((void**)&cur_ptr, g_cur);

    // fork: s1 = cursor reset + scatter (depends only on idx arrays)
    cudaEventRecord(evA, s0);
    cudaStreamWaitEvent(s1, evA, 0);
    cudaMemsetAsync(cur_ptr, 0, NOUT * KPAD * sizeof(int), s1);
    int nq = nnz >> 2;
    k_scatter4<<<(nq + 255) / 256, 256, 0, s1>>>(
        (const int4*)idx_k, (const int4*)idx_o, (const int4*)idx_i,
        (const float4*)psi, nq);
    int rem = nnz - (nq << 2);
    if (rem > 0)
        k_scatter_tail<<<1, 256, 0, s1>>>(idx_k, idx_o, idx_i, psi, nq << 2, nnz);
    cudaEventRecord(evB, s1);

    // main stream: xq + wT2 prep
    dim3 tb(32, 32);
    k_xqT<<<dim3(NIN / 32, 64 / 32), tb, 0, s0>>>(x, qw);
    k_wT2<<<(KS * 32 * 32 + 255) / 256, 256, 0, s0>>>(wgt);

    // join, then fused gather+mix
    cudaStreamWaitEvent(s0, evB, 0);
    k_gather<<<GBLOCKS, 512, GATHER_SMEM, s0>>>(bias, out);
}